// round 6
// baseline (speedup 1.0000x reference)
#include <cuda_runtime.h>
#include <cstdint>

#define N     8192
#define K1    31
#define CAP   256      // per-line candidate capacity (mean 88, max ~135)
#define PIVOT 2.3f     // P(z>2.3)=0.0107
#define NF4   ((size_t)N * N / 4)

__device__ unsigned int       g_bits[(size_t)N * N / 32];  // 8 MB candidate bitmask
__device__ unsigned long long g_rowcand[(size_t)N * CAP];  // 16 MB
__device__ unsigned long long g_colcand[(size_t)N * CAP];  // 16 MB
__device__ int                g_rowcnt[N];
__device__ int                g_colcnt[N];
__device__ unsigned long long g_rowth[N];
__device__ unsigned long long g_colth[N];

// Monotone map float -> uint32 (larger float => larger key)
__device__ __forceinline__ unsigned int fkey(float x) {
    unsigned int u = __float_as_uint(x);
    return (u & 0x80000000u) ? ~u : (u | 0x80000000u);
}
__device__ __forceinline__ float inv_fkey(unsigned int k) {
    unsigned int u = (k & 0x80000000u) ? (k ^ 0x80000000u) : ~k;
    return __uint_as_float(u);
}
// Composite key: value-major, lower index wins ties (stable top_k semantics)
__device__ __forceinline__ unsigned long long ckey(float x, int idx) {
    return ((unsigned long long)fkey(x) << 32) | (unsigned int)(N - 1 - idx);
}

__global__ void zero_kernel() {
    int t = blockIdx.x * blockDim.x + threadIdx.x;
    if (t < N) g_colcnt[t] = 0;
}

// --- generic fallback: K1-th largest composite key of a full line (exact) ---
template <bool ROW, int BT>
__device__ unsigned long long fallback_select(const float* __restrict__ A, int line) {
    __shared__ unsigned long long red[BT];
    unsigned long long prev = 0xFFFFFFFFFFFFFFFFull;
    for (int it = 0; it < K1; it++) {
        unsigned long long best = 0;
        for (int t = threadIdx.x; t < N; t += BT) {
            float x = ROW ? A[(size_t)line * N + t] : A[(size_t)t * N + line];
            unsigned long long k = ckey(x, t);
            if (k < prev && k > best) best = k;
        }
        red[threadIdx.x] = best;
        __syncthreads();
        for (int s = BT / 2; s > 0; s >>= 1) {
            if (threadIdx.x < s) {
                unsigned long long o = red[threadIdx.x + s];
                if (o > red[threadIdx.x]) red[threadIdx.x] = o;
            }
            __syncthreads();
        }
        prev = red[0];
        __syncthreads();
    }
    return prev;
}

// K1: PURE streaming pass (mask_kernel shape). Reads A, writes zeros to out,
// emits candidate bitmask via warp ballots. No atomics, no barriers.
// Bit layout: global warp gw covers elements [gw*128, gw*128+128);
// word gw*4+c, bit `lane`  <->  element gw*128 + lane*4 + c.
__global__ __launch_bounds__(256) void stream_kernel(const float* __restrict__ A,
                                                     float* __restrict__ out) {
    const size_t g = (size_t)blockIdx.x * 256 + threadIdx.x;  // float4 index
    float4 v = ((const float4*)A)[g];
    const float4 zz = {0.0f, 0.0f, 0.0f, 0.0f};
    ((float4*)out)[g] = zz;
    unsigned m0 = __ballot_sync(0xFFFFFFFFu, v.x > PIVOT);
    unsigned m1 = __ballot_sync(0xFFFFFFFFu, v.y > PIVOT);
    unsigned m2 = __ballot_sync(0xFFFFFFFFu, v.z > PIVOT);
    unsigned m3 = __ballot_sync(0xFFFFFFFFu, v.w > PIVOT);
    if ((threadIdx.x & 31) == 0) {
        size_t gw = g >> 5;  // global warp index
        uint4 w = {m0, m1, m2, m3};
        ((uint4*)g_bits)[gw] = w;
    }
}

// K2: block per row. Decode bitmask -> row candidate list (scan, no atomics),
// compute rowth, store list for scatter; push column candidates (spread atomics).
__global__ __launch_bounds__(256) void rowcand_kernel(const float* __restrict__ A) {
    const int i = blockIdx.x, t = threadIdx.x;
    unsigned w = g_bits[(size_t)i * 256 + t];   // 256 words per row
    int cnt = __popc(w);

    __shared__ int sc[256];
    sc[t] = cnt;
    __syncthreads();
#pragma unroll
    for (int d = 1; d < 256; d <<= 1) {
        int v = (t >= d) ? sc[t - d] : 0;
        __syncthreads();
        sc[t] += v;
        __syncthreads();
    }
    const int total = sc[255];
    int off = sc[t] - cnt;   // exclusive prefix

    __shared__ unsigned long long cand[CAP];
    const int seg = t >> 2, c = t & 3;
    unsigned wb = w;
    while (wb) {
        int lane = __ffs(wb) - 1;
        wb &= wb - 1;
        int j = seg * 128 + lane * 4 + c;
        float x = A[(size_t)i * N + j];
        if (off < CAP) cand[off] = ckey(x, j);
        off++;
        int cs = atomicAdd(&g_colcnt[j], 1);
        if (cs < CAP) g_colcand[(size_t)j * CAP + cs] = ckey(x, i);
    }
    __syncthreads();
    if (t == 0) g_rowcnt[i] = total;

    if (total >= K1 && total <= CAP) {
        for (int s = t; s < total; s += 256) {
            unsigned long long kt = cand[s];
            int r = 0;
            for (int m = 0; m < total; m++) r += (cand[m] > kt);
            if (r == K1 - 1) g_rowth[i] = kt;
            g_rowcand[(size_t)i * CAP + s] = kt;   // list for scatter
        }
    } else {
        unsigned long long th = fallback_select<true, 256>(A, i);
        if (t == 0) g_rowth[i] = th;
    }
}

// K3: column thresholds from column candidate lists (exact fallback on under/overflow).
__global__ __launch_bounds__(128) void colth_kernel(const float* __restrict__ A) {
    const int j = blockIdx.x;
    const int c = g_colcnt[j];
    __shared__ unsigned long long cand[CAP];
    if (c >= K1 && c <= CAP) {
        for (int t = threadIdx.x; t < c; t += 128)
            cand[t] = g_colcand[(size_t)j * CAP + t];
        __syncthreads();
        for (int t = threadIdx.x; t < c; t += 128) {
            unsigned long long kt = cand[t];
            int r = 0;
            for (int m = 0; m < c; m++) r += (cand[m] > kt);
            if (r == K1 - 1) g_colth[j] = kt;
        }
    } else {
        unsigned long long th = fallback_select<false, 128>(A, j);
        if (threadIdx.x == 0) g_colth[j] = th;
    }
}

// K4: scatter survivors from ROW lists (row-major writes). Any element passing
// rowth with value <= PIVOT implies row underflow -> full row rescan (exact).
__global__ __launch_bounds__(128) void scatter_kernel(const float* __restrict__ A,
                                                      float* __restrict__ out) {
    const int i = blockIdx.x;
    const int c = g_rowcnt[i];
    const unsigned long long rth = g_rowth[i];
    if (c >= K1 && c <= CAP) {
        for (int s = threadIdx.x; s < c; s += 128) {
            unsigned long long k = g_rowcand[(size_t)i * CAP + s];
            if (k < rth) continue;
            int j = N - 1 - (int)(unsigned int)(k & 0xFFFFFFFFu);
            if (j == i) continue;
            float x = inv_fkey((unsigned int)(k >> 32));
            if (ckey(x, i) >= g_colth[j])
                out[(size_t)i * N + j] = x;
        }
    } else {
        for (int j = threadIdx.x; j < N; j += 128) {
            if (j == i) continue;
            float x = A[(size_t)i * N + j];
            if (ckey(x, j) >= rth && ckey(x, i) >= g_colth[j])
                out[(size_t)i * N + j] = x;
        }
    }
}

extern "C" void kernel_launch(void* const* d_in, const int* in_sizes, int n_in,
                              void* d_out, int out_size) {
    const float* A = (const float*)d_in[0];
    float* out = (float*)d_out;
    zero_kernel<<<(N + 255) / 256, 256>>>();
    stream_kernel<<<(unsigned)(NF4 / 256), 256>>>(A, out);
    rowcand_kernel<<<N, 256>>>(A);
    colth_kernel<<<N, 128>>>(A);
    scatter_kernel<<<N, 128>>>(A, out);
}